// round 14
// baseline (speedup 1.0000x reference)
#include <cuda_runtime.h>
#include <math.h>
#include <stdint.h>

#define MEMN 32768
#define BATCH 256
#define UNITS 128
#define IN_DIM 512

#define OFF_READ    0
#define OFF_MEMORY  (OFF_READ + BATCH*UNITS)
#define OFF_CWU     (OFF_MEMORY + MEMN*UNITS)
#define OFF_CWLU    (OFF_CWU + MEMN*BATCH)
#define OFF_CWR     (OFF_CWLU + MEMN*BATCH)
#define OFF_CWW     (OFF_CWR + MEMN*BATCH)
#define OFF_H       (OFF_CWW + MEMN*BATCH)
#define OFF_C       (OFF_H + BATCH*UNITS)

#define PA 132
#define PB 136

typedef unsigned long long ull;

// scratch (device globals: no allocation allowed)
__device__ float g_h[BATCH*UNITS];
__device__ float g_hT[UNITS*BATCH];          // [unit][batch]
__device__ float g_kinv[BATCH];
__device__ ull   g_colenc[BATCH];
__device__ float g_colmin[BATCH];
__device__ int   g_cnt[MEMN];

__device__ __forceinline__ unsigned ordf(float f) {
    unsigned u = __float_as_uint(f);
    return (u & 0x80000000u) ? ~u : (u | 0x80000000u);
}

__device__ __forceinline__ void mma_tf32(float* d, const unsigned* a, const unsigned* b) {
    asm volatile(
        "mma.sync.aligned.m16n8k8.row.col.f32.tf32.tf32.f32 "
        "{%0,%1,%2,%3}, {%4,%5,%6,%7}, {%8,%9}, {%0,%1,%2,%3};"
        : "+f"(d[0]), "+f"(d[1]), "+f"(d[2]), "+f"(d[3])
        : "r"(a[0]), "r"(a[1]), "r"(a[2]), "r"(a[3]), "r"(b[0]), "r"(b[1]));
}

__device__ __forceinline__ unsigned rna_tf32(float a) {
    unsigned r;
    asm("cvt.rna.tf32.f32 %0, %1;" : "=r"(r) : "f"(a));
    return r;
}
__device__ __forceinline__ void split2(float a, unsigned& hi, unsigned& lo) {
    unsigned h;
    asm("cvt.rna.tf32.f32 %0, %1;" : "=r"(h) : "f"(a));
    hi = h;
    lo = __float_as_uint(a - __uint_as_float(h));
}

// ---------------- init ----------------
__global__ void k_init(float* __restrict__ out_read) {
    int i = blockIdx.x * 256 + threadIdx.x;
    if (i < MEMN) g_cnt[i] = 0;
    if (i < BATCH*UNITS) out_read[i] = 0.f;
    if (i < BATCH) g_colenc[i] = 0xFFFFFFFFFFFFFFFFull;
}

// ---------------- LSTM cell ----------------
__global__ void k_lstm(const float* __restrict__ inputs, const float* __restrict__ r_tm1,
                       const float* __restrict__ h_tm1, const float* __restrict__ c_tm1,
                       const float* __restrict__ Wk, const float* __restrict__ Wr,
                       const float* __restrict__ bias, float* __restrict__ out) {
    __shared__ float sA[16][128];
    __shared__ float sB[128][64];
    int t = threadIdx.x;
    int utile = blockIdx.x, btile = blockIdx.y;
    int ul = t & 15, bl = t >> 4;
    float acc[4] = {0.f, 0.f, 0.f, 0.f};

    for (int kc = 0; kc < 6; kc++) {
        #pragma unroll
        for (int p = 0; p < 2; p++) {
            int i = t + p * 256;
            int row = i >> 5, c4 = (i & 31) * 4;
            int b = btile * 16 + row;
            const float* src;
            if (kc < 4)       src = inputs + b * IN_DIM + kc * 128 + c4;
            else if (kc == 4) src = r_tm1 + b * UNITS + c4;
            else              src = h_tm1 + b * UNITS + c4;
            *(float4*)&sA[row][c4] = *(const float4*)src;
        }
        #pragma unroll
        for (int p = 0; p < 8; p++) {
            int i = t + p * 256;
            int k = i >> 4, c4 = (i & 15) * 4;
            int q = c4 >> 4, jr = c4 & 15;
            int jc = utile * 16 + jr + q * 128;
            float4 v;
            if (kc < 5) v = *(const float4*)(Wk + (kc * 128 + k) * 512 + jc);
            else        v = *(const float4*)(Wr + k * 512 + jc);
            *(float4*)&sB[k][c4] = v;
        }
        __syncthreads();
        #pragma unroll 8
        for (int k = 0; k < 128; k++) {
            float a = sA[bl][k];
            acc[0] += a * sB[k][ul];
            acc[1] += a * sB[k][16 + ul];
            acc[2] += a * sB[k][32 + ul];
            acc[3] += a * sB[k][48 + ul];
        }
        __syncthreads();
    }
    int b = btile * 16 + bl, u = utile * 16 + ul;
    float zi = acc[0] + bias[u];
    float zf = acc[1] + bias[128 + u];
    float zg = acc[2] + bias[256 + u];
    float zo = acc[3] + bias[384 + u];
    float si = 1.f / (1.f + expf(-zi));
    float sf = 1.f / (1.f + expf(-zf));
    float so = 1.f / (1.f + expf(-zo));
    float cn = sf * c_tm1[b * UNITS + u] + si * tanhf(zg);
    float hn = so * tanhf(cn);
    out[OFF_H + b * UNITS + u] = hn;
    out[OFF_C + b * UNITS + u] = cn;
    g_h[b * UNITS + u] = hn;
}

// ---------------- key inverse norms + h transpose ----------------
__global__ void k_knorm() {
    int t = threadIdx.x, w = t >> 5, l = t & 31;
    int b = blockIdx.x * 8 + w;
    float s = 0.f;
    #pragma unroll
    for (int i = 0; i < 4; i++) { float v = g_h[b * UNITS + l + 32 * i]; s += v * v; }
    #pragma unroll
    for (int o = 16; o; o >>= 1) s += __shfl_xor_sync(0xffffffffu, s, o);
    if (l == 0) g_kinv[b] = rsqrtf(fmaxf(s, 1e-12f));
    #pragma unroll
    for (int p = 0; p < 4; p++) {
        int idx = blockIdx.x * 1024 + p * 256 + t;
        g_hT[(idx & 127) * BATCH + (idx >> 7)] = g_h[idx];
    }
}

// ---------------- FUSED: cos GEMM + softmax + ww/wu + col-min --------------
// grid 1024 (32 m-rows each), 256 thr, 8 warps, warp tile 32m x 32n.
// B staged in 4 chunks of 32 rows -> smem 54.6KB -> 3 CTAs/SM.
// smem: sA[32][132] | sB[32][264] | sKinv[256] | sSS[32] | sRmax[32][8] | sRsum[32][8] | sEnc[256]
__global__ void __launch_bounds__(256, 3)
k_fuse(const float* __restrict__ mptr, const float* __restrict__ wr_tm1,
       const float* __restrict__ wlu_tm1, const float* __restrict__ wu_tm1,
       const float* __restrict__ wgate, float* __restrict__ out) {
    extern __shared__ float sm[];
    float* sA    = sm;                       // 32*132 = 4224
    float* sB    = sA + 32 * 132;            // 32*264 = 8448 (mainloop B chunk; later wr staging)
    float* sKinv = sB + 32 * 264;            // 256
    float* sSS   = sKinv + 256;              // 32
    float* sRmax = sSS + 32;                 // 256 ([32][8])
    float* sRsum = sRmax + 256;              // 256
    ull*   sEnc  = (ull*)(sRsum + 256);      // 256 ull
    float* sWr   = sB;                       // [32][264] staging

    int t = threadIdx.x;
    int lane = t & 31, wid = t >> 5;
    int qr = lane >> 2, qc = lane & 3;
    int mbase = blockIdx.x * 32;
    int wn = wid * 32;

    // stage A [32 rows][128 k]
    #pragma unroll
    for (int i = 0; i < 4; i++) {
        int g = t + i * 256;
        int r = g >> 5, c4 = (g & 31) << 2;
        *(float4*)&sA[r * 132 + c4] = *(const float4*)(mptr + (mbase + r) * UNITS + c4);
    }
    sKinv[t] = g_kinv[t];
    sEnc[t] = 0xFFFFFFFFFFFFFFFFull;
    __syncthreads();
    if (t < 32) {
        float ss = 0.f;
        #pragma unroll
        for (int i = 0; i < 32; i++) {
            float4 v = *(float4*)&sA[t * 132 + i * 4];
            ss += v.x * v.x + v.y * v.y + v.z * v.z + v.w * v.w;
        }
        sSS[t] = rsqrtf(fmaxf(ss, 1e-12f));
    }

    float acc[2][4][4];
    #pragma unroll
    for (int i = 0; i < 2; i++)
        #pragma unroll
        for (int j = 0; j < 4; j++)
            #pragma unroll
            for (int q = 0; q < 4; q++) acc[i][j][q] = 0.f;

    for (int kc = 0; kc < 4; kc++) {
        // stage B chunk: hT rows [kc*32 .. +31] x 256 batch
        #pragma unroll
        for (int i = 0; i < 8; i++) {
            int g = t + i * 256;
            int r = g >> 6, c4 = (g & 63) << 2;
            *(float4*)&sB[r * 264 + c4] = *(const float4*)(g_hT + (kc * 32 + r) * BATCH + c4);
        }
        __syncthreads();
        #pragma unroll
        for (int ks = 0; ks < 4; ks++) {
            int kbA = kc * 32 + ks * 8;
            int kbB = ks * 8;
            unsigned ah[2][4], al[2][4], bb[4][2];
            #pragma unroll
            for (int mt = 0; mt < 2; mt++) {
                int rb = mt * 16;
                split2(sA[(rb + qr) * 132 + kbA + qc],         ah[mt][0], al[mt][0]);
                split2(sA[(rb + 8 + qr) * 132 + kbA + qc],     ah[mt][1], al[mt][1]);
                split2(sA[(rb + qr) * 132 + kbA + 4 + qc],     ah[mt][2], al[mt][2]);
                split2(sA[(rb + 8 + qr) * 132 + kbA + 4 + qc], ah[mt][3], al[mt][3]);
            }
            #pragma unroll
            for (int nt = 0; nt < 4; nt++) {
                int cb = wn + nt * 8;
                bb[nt][0] = rna_tf32(sB[(kbB + qc) * 264 + cb + qr]);
                bb[nt][1] = rna_tf32(sB[(kbB + 4 + qc) * 264 + cb + qr]);
            }
            #pragma unroll
            for (int mt = 0; mt < 2; mt++)
                #pragma unroll
                for (int nt = 0; nt < 4; nt++) {
                    mma_tf32(acc[mt][nt], ah[mt], bb[nt]);
                    mma_tf32(acc[mt][nt], al[mt], bb[nt]);
                }
        }
        __syncthreads();
    }

    // ---- scale to cosine ----
    #pragma unroll
    for (int mt = 0; mt < 2; mt++) {
        float s0 = sSS[mt * 16 + qr];
        float s1 = sSS[mt * 16 + qr + 8];
        #pragma unroll
        for (int nt = 0; nt < 4; nt++) {
            float k0 = sKinv[wn + nt * 8 + 2 * qc];
            float k1 = sKinv[wn + nt * 8 + 2 * qc + 1];
            acc[mt][nt][0] *= s0 * k0;
            acc[mt][nt][1] *= s0 * k1;
            acc[mt][nt][2] *= s1 * k0;
            acc[mt][nt][3] *= s1 * k1;
        }
    }

    // ---- row max ----
    float rmax[2][2];
    #pragma unroll
    for (int mt = 0; mt < 2; mt++)
        #pragma unroll
        for (int h = 0; h < 2; h++) {
            float m = -1e30f;
            #pragma unroll
            for (int nt = 0; nt < 4; nt++) {
                m = fmaxf(m, acc[mt][nt][2 * h]);
                m = fmaxf(m, acc[mt][nt][2 * h + 1]);
            }
            m = fmaxf(m, __shfl_xor_sync(0xffffffffu, m, 1));
            m = fmaxf(m, __shfl_xor_sync(0xffffffffu, m, 2));
            rmax[mt][h] = m;
        }
    if (qc == 0) {
        #pragma unroll
        for (int mt = 0; mt < 2; mt++)
            #pragma unroll
            for (int h = 0; h < 2; h++)
                sRmax[(mt * 16 + qr + h * 8) * 8 + wid] = rmax[mt][h];
    }
    __syncthreads();
    #pragma unroll
    for (int mt = 0; mt < 2; mt++)
        #pragma unroll
        for (int h = 0; h < 2; h++) {
            int rl = (mt * 16 + qr + h * 8) * 8;
            float m = sRmax[rl];
            #pragma unroll
            for (int q = 1; q < 8; q++) m = fmaxf(m, sRmax[rl + q]);
            rmax[mt][h] = m;
        }

    // ---- exp in place + row sum ----
    float rsum[2][2];
    #pragma unroll
    for (int mt = 0; mt < 2; mt++)
        #pragma unroll
        for (int h = 0; h < 2; h++) {
            float s = 0.f;
            float m = rmax[mt][h];
            #pragma unroll
            for (int nt = 0; nt < 4; nt++) {
                float e0 = __expf(acc[mt][nt][2 * h] - m);
                float e1 = __expf(acc[mt][nt][2 * h + 1] - m);
                acc[mt][nt][2 * h] = e0;
                acc[mt][nt][2 * h + 1] = e1;
                s += e0 + e1;
            }
            s += __shfl_xor_sync(0xffffffffu, s, 1);
            s += __shfl_xor_sync(0xffffffffu, s, 2);
            rsum[mt][h] = s;
        }
    if (qc == 0) {
        #pragma unroll
        for (int mt = 0; mt < 2; mt++)
            #pragma unroll
            for (int h = 0; h < 2; h++)
                sRsum[(mt * 16 + qr + h * 8) * 8 + wid] = rsum[mt][h];
    }
    __syncthreads();
    float rinv[2][2];
    #pragma unroll
    for (int mt = 0; mt < 2; mt++)
        #pragma unroll
        for (int h = 0; h < 2; h++) {
            int rl = (mt * 16 + qr + h * 8) * 8;
            float s = sRsum[rl];
            #pragma unroll
            for (int q = 1; q < 8; q++) s += sRsum[rl + q];
            rinv[mt][h] = 1.f / s;
        }
    __syncthreads();   // all reads of sB (mainloop) and sums done; reuse sB as sWr

    // ---- stage wr into smem ----
    #pragma unroll
    for (int mt = 0; mt < 2; mt++)
        #pragma unroll
        for (int h = 0; h < 2; h++) {
            int rowl = mt * 16 + qr + h * 8;
            float inv = rinv[mt][h];
            #pragma unroll
            for (int nt = 0; nt < 4; nt++) {
                int col = wn + nt * 8 + 2 * qc;
                float2 wrp = make_float2(acc[mt][nt][2 * h] * inv, acc[mt][nt][2 * h + 1] * inv);
                *(float2*)&sWr[rowl * 264 + col] = wrp;
            }
        }
    __syncthreads();

    // ---- coalesced epilogue: thread t owns col-float4 (t&63), rows (t>>6)+4i ----
    float wg = 1.f / (1.f + __expf(-wgate[0]));
    float omw = 1.f - wg;
    int col4 = (t & 63) * 4;
    ull emin[4] = {~0ull, ~0ull, ~0ull, ~0ull};

    #pragma unroll 4
    for (int i = 0; i < 8; i++) {
        int rowl = (t >> 6) + i * 4;
        int rg = mbase + rowl;
        int idx = rg * BATCH + col4;
        float4 wr4 = *(float4*)&sWr[rowl * 264 + col4];
        float4 wrt = *(const float4*)(wr_tm1 + idx);
        float4 wlt = *(const float4*)(wlu_tm1 + idx);
        float4 wut = *(const float4*)(wu_tm1 + idx);
        float4 ww4, wu4;
        ww4.x = wg * wrt.x + omw + wlt.x;  ww4.y = wg * wrt.y + omw + wlt.y;
        ww4.z = wg * wrt.z + omw + wlt.z;  ww4.w = wg * wrt.w + omw + wlt.w;
        wu4.x = 0.95f * wut.x + wr4.x + ww4.x;  wu4.y = 0.95f * wut.y + wr4.y + ww4.y;
        wu4.z = 0.95f * wut.z + wr4.z + ww4.z;  wu4.w = 0.95f * wut.w + wr4.w + ww4.w;
        *(float4*)&out[OFF_CWR + idx] = wr4;
        *(float4*)&out[OFF_CWW + idx] = ww4;
        *(float4*)&out[OFF_CWU + idx] = wu4;
        ull lw = (ull)(0xFFFFFFFFu - (unsigned)rg);
        ull e0 = ((ull)ordf(wu4.x) << 32) | lw;
        ull e1 = ((ull)ordf(wu4.y) << 32) | lw;
        ull e2 = ((ull)ordf(wu4.z) << 32) | lw;
        ull e3 = ((ull)ordf(wu4.w) << 32) | lw;
        emin[0] = (e0 < emin[0]) ? e0 : emin[0];
        emin[1] = (e1 < emin[1]) ? e1 : emin[1];
        emin[2] = (e2 < emin[2]) ? e2 : emin[2];
        emin[3] = (e3 < emin[3]) ? e3 : emin[3];
    }
    #pragma unroll
    for (int j = 0; j < 4; j++)
        atomicMin(&sEnc[col4 + j], emin[j]);
    __syncthreads();
    atomicMin(&g_colenc[t], sEnc[t]);
}

// ---------------- finalize argmin ---------------- 1 x 256
__global__ void k_fin() {
    int c = threadIdx.x;
    ull e = g_colenc[c];
    unsigned hi = (unsigned)(e >> 32);
    unsigned bits = (hi & 0x80000000u) ? (hi & 0x7FFFFFFFu) : ~hi;
    g_colmin[c] = __uint_as_float(bits);
    int idx = (int)(0xFFFFFFFFu - (unsigned)(e & 0xFFFFFFFFull));
    atomicAdd(&g_cnt[idx], 1);
}

// ---------------- read = c_wr.T @ m_tm1, 2-MMA split, split-K, dbl-buffered -
#define RD_WO (64 * 72)
#define RD_MO (64 * 136)
#define RD_LOAD(it, buf) { \
    int kb0 = kchunk * 512 + (it) * 64; \
    _Pragma("unroll") \
    for (int i = 0; i < 4; i++) { \
        int g = t + i * 256; \
        int r = g >> 4, c4 = (g & 15) << 2; \
        *(float4*)&sW[(buf) * RD_WO + r * 72 + c4] = *(const float4*)(cwr + (kb0 + r) * BATCH + bbase + c4); \
    } \
    _Pragma("unroll") \
    for (int i = 0; i < 8; i++) { \
        int g = t + i * 256; \
        int r = g >> 5, c4 = (g & 31) << 2; \
        *(float4*)&sM[(buf) * RD_MO + r * 136 + c4] = *(const float4*)(mptr + (kb0 + r) * UNITS + c4); \
    } \
}

__global__ void __launch_bounds__(256, 2) k_read(const float* __restrict__ mptr,
                                                 const float* __restrict__ cwr,
                                                 float* __restrict__ out_read) {
    extern __shared__ float sm[];
    float* sW = sm;                      // [2][64][72]
    float* sM = sm + 2 * RD_WO;          // [2][64][136]

    int t = threadIdx.x;
    int lane = t & 31, wid = t >> 5;
    int qr = lane >> 2, qc = lane & 3;
    int bbase = blockIdx.x * 64;
    int kchunk = blockIdx.y;
    int wm = (wid >> 2) * 32, wn = (wid & 3) * 32;

    float acc[2][4][4];
    #pragma unroll
    for (int i = 0; i < 2; i++)
        #pragma unroll
        for (int j = 0; j < 4; j++)
            #pragma unroll
            for (int q = 0; q < 4; q++) acc[i][j][q] = 0.f;

    RD_LOAD(0, 0);
    __syncthreads();

    for (int it = 0; it < 8; it++) {
        int buf = it & 1;
        if (it < 7) { RD_LOAD(it + 1, buf ^ 1); }
        const float* cW = sW + buf * RD_WO;
        const float* cM = sM + buf * RD_MO;
        #pragma unroll
        for (int ks = 0; ks < 8; ks++) {
            int kb = ks * 8;
            unsigned ah[2][4], al[2][4], bb[4][2];
            #pragma unroll
            for (int mt = 0; mt < 2; mt++) {
                int rb = wm + mt * 16;
                split2(cW[(kb + qc) * 72 + rb + qr],         ah[mt][0], al[mt][0]);
                split2(cW[(kb + qc) * 72 + rb + 8 + qr],     ah[mt][1], al[mt][1]);
                split2(cW[(kb + 4 + qc) * 72 + rb + qr],     ah[mt][2], al[mt][2]);
                split2(cW[(kb + 4 + qc) * 72 + rb + 8 + qr], ah[mt][3], al[mt][3]);
            }
            #pragma unroll
            for (int nt = 0; nt < 4; nt++) {
                int cb = wn + nt * 8;
                bb[nt][0] = rna_tf32(cM[(kb + qc) * 136 + cb + qr]);
                bb[nt][1] = rna_tf32(cM[(kb + 4 + qc) * 136 + cb + qr]);
            }
            #pragma unroll
            for (int mt = 0; mt < 2; mt++)
                #pragma unroll
                for (int nt = 0; nt < 4; nt++) {
                    mma_tf32(acc[mt][nt], ah[mt], bb[nt]);
                    mma_tf32(acc[mt][nt], al[mt], bb[nt]);
                }
        }
        __syncthreads();
    }
    #pragma unroll
    for (int mt = 0; mt < 2; mt++) {
        int r0 = bbase + wm + mt * 16 + qr;
        #pragma unroll
        for (int nt = 0; nt < 4; nt++) {
            int c = wn + nt * 8 + 2 * qc;
            atomicAdd(&out_read[r0 * UNITS + c],           acc[mt][nt][0]);
            atomicAdd(&out_read[r0 * UNITS + c + 1],       acc[mt][nt][1]);
            atomicAdd(&out_read[(r0 + 8) * UNITS + c],     acc[mt][nt][2]);
            atomicAdd(&out_read[(r0 + 8) * UNITS + c + 1], acc[mt][nt][3]);
        }
    }
}

// ---------------- memory = c_ww @ h + (256 - cnt[m]) * m_tm1 ---------------
__global__ void __launch_bounds__(256) k_mem(const float* __restrict__ mptr,
                                             const float* __restrict__ cww,
                                             float* __restrict__ out_mem) {
    extern __shared__ float sm[];
    float* sA = sm;                  // [64][PA]
    float* sB = sm + 64 * PA;        // [128][PB]

    int t = threadIdx.x;
    int lane = t & 31, wid = t >> 5;
    int qr = lane >> 2, qc = lane & 3;
    int mbase = blockIdx.x * 64;
    int wm = (wid >> 2) * 32, wn = (wid & 3) * 32;

    float acc[2][4][4];
    #pragma unroll
    for (int i = 0; i < 2; i++)
        #pragma unroll
        for (int j = 0; j < 4; j++)
            #pragma unroll
            for (int q = 0; q < 4; q++) acc[i][j][q] = 0.f;

    for (int kc = 0; kc < 2; kc++) {
        #pragma unroll
        for (int i = 0; i < 8; i++) {
            int g = t + i * 256;
            int r = g >> 5, c4 = (g & 31) << 2;
            *(float4*)&sA[r * PA + c4] = *(const float4*)(cww + (mbase + r) * BATCH + kc * 128 + c4);
        }
        #pragma unroll
        for (int i = 0; i < 16; i++) {
            int g = t + i * 256;
            int r = g >> 5, c4 = (g & 31) << 2;
            *(float4*)&sB[r * PB + c4] = *(const float4*)(g_h + (kc * 128 + r) * UNITS + c4);
        }
        __syncthreads();
        #pragma unroll
        for (int ks = 0; ks < 16; ks++) {
            int kb = ks * 8;
            unsigned ah[2][4], al[2][4], bb[4][2];
            #pragma unroll
            for (int mt = 0; mt < 2; mt++) {
                int rb = wm + mt * 16;
                split2(sA[(rb + qr) * PA + kb + qc],         ah[mt][0], al[mt][0]);
                split2(sA[(rb + 8 + qr) * PA + kb + qc],     ah[mt][1], al[mt][1]);
                split2(sA[(rb + qr) * PA + kb + 4 + qc],     ah[mt][2], al[mt][2]);
                split2(sA[(rb + 8 + qr) * PA + kb + 4 + qc], ah[mt][3], al[mt][3]);
            }
            #pragma unroll
            for (int nt = 0; nt < 4; nt++) {
                int cb = wn + nt * 8;
                bb[nt][0] = rna_tf32(sB[(kb + qc) * PB + cb + qr]);
                bb[nt][1] = rna_tf32(sB[(kb + 4 + qc) * PB + cb + qr]);
            }
            #pragma unroll
            for (int mt = 0; mt < 2; mt++)
                #pragma unroll
                for (int nt = 0; nt < 4; nt++) {
                    mma_tf32(acc[mt][nt], ah[mt], bb[nt]);
                    mma_tf32(acc[mt][nt], al[mt], bb[nt]);
                }
        }
        __syncthreads();
    }

    // ---- stage result fragments into smem (sA dead) ----
    #pragma unroll
    for (int mt = 0; mt < 2; mt++) {
        int rowl = wm + mt * 16 + qr;
        #pragma unroll
        for (int nt = 0; nt < 4; nt++) {
            int c = wn + nt * 8 + 2 * qc;
            *(float2*)&sA[rowl * PA + c]       = make_float2(acc[mt][nt][0], acc[mt][nt][1]);
            *(float2*)&sA[(rowl + 8) * PA + c] = make_float2(acc[mt][nt][2], acc[mt][nt][3]);
        }
    }
    __syncthreads();

    // ---- coalesced pass: warp owns a full 128-float row ----
    int colq = lane * 4;
    #pragma unroll
    for (int i = 0; i < 8; i++) {
        int rowl = wid + i * 8;
        int rg = mbase + rowl;
        float f = (float)(BATCH - g_cnt[rg]);
        float4 mv = *(const float4*)(mptr + rg * UNITS + colq);
        float4 rv = *(float4*)&sA[rowl * PA + colq];
        float4 o;
        o.x = rv.x + f * mv.x;
        o.y = rv.y + f * mv.y;
        o.z = rv.z + f * mv.z;
        o.w = rv.w + f * mv.w;
        *(float4*)(out_mem + rg * UNITS + colq) = o;
    }
}

// ---------------- c_wlu = (c_wu <= colmin) ----------------
__global__ void k_wlu(const float* __restrict__ out_cwu, float* __restrict__ out_cwlu) {
    __shared__ float smin[256];
    smin[threadIdx.x] = g_colmin[threadIdx.x];
    __syncthreads();
    const int total = MEMN * BATCH / 4;
    for (int i4 = blockIdx.x * 256 + threadIdx.x; i4 < total; i4 += gridDim.x * 256) {
        float4 v = *(const float4*)(out_cwu + i4 * 4);
        int c = (i4 & 63) * 4;
        float4 o;
        o.x = (v.x <= smin[c])     ? 1.f : 0.f;
        o.y = (v.y <= smin[c + 1]) ? 1.f : 0.f;
        o.z = (v.z <= smin[c + 2]) ? 1.f : 0.f;
        o.w = (v.w <= smin[c + 3]) ? 1.f : 0.f;
        *(float4*)(out_cwlu + i4 * 4) = o;
    }
}

extern "C" void kernel_launch(void* const* d_in, const int* in_sizes, int n_in,
                              void* d_out, int out_size) {
    (void)in_sizes; (void)n_in; (void)out_size;
    const float* inputs   = (const float*)d_in[0];
    const float* r_tm1    = (const float*)d_in[1];
    const float* m_tm1    = (const float*)d_in[2];
    const float* c_wu_tm1 = (const float*)d_in[3];
    const float* c_wlu_tm1= (const float*)d_in[4];
    const float* c_wr_tm1 = (const float*)d_in[5];
    const float* h_tm1    = (const float*)d_in[7];
    const float* c_tm1    = (const float*)d_in[8];
    const float* Wk       = (const float*)d_in[9];
    const float* Wr       = (const float*)d_in[10];
    const float* bias     = (const float*)d_in[11];
    const float* wgate    = (const float*)d_in[12];
    float* out = (float*)d_out;

    const int smem_fuse = (32 * 132 + 32 * 264 + 256 + 32 + 256 + 256 + 512) * 4;  // 55936
    const int smem_read = 2 * (RD_WO + RD_MO) * 4;                                 // 106496
    const int smem_mem  = (64 * PA + 128 * PB) * 4;                                // 103424

    cudaFuncSetAttribute(k_fuse, cudaFuncAttributeMaxDynamicSharedMemorySize, smem_fuse);
    cudaFuncSetAttribute(k_read, cudaFuncAttributeMaxDynamicSharedMemorySize, smem_read);
    cudaFuncSetAttribute(k_mem,  cudaFuncAttributeMaxDynamicSharedMemorySize, smem_mem);

    k_init<<<128, 256>>>(out + OFF_READ);
    k_lstm<<<dim3(8, 16), 256>>>(inputs, r_tm1, h_tm1, c_tm1, Wk, Wr, bias, out);
    k_knorm<<<32, 256>>>();
    k_fuse<<<1024, 256, smem_fuse>>>(m_tm1, c_wr_tm1, c_wlu_tm1, c_wu_tm1, wgate, out);
    k_fin<<<1, 256>>>();
    k_read<<<dim3(4, 64), 256, smem_read>>>(m_tm1, out + OFF_CWR, out + OFF_READ);
    k_mem<<<512, 256, smem_mem>>>(m_tm1, out + OFF_CWW, out + OFF_MEMORY);
    k_wlu<<<2048, 256>>>(out + OFF_CWU, out + OFF_CWLU);
}

// round 15
// speedup vs baseline: 1.3719x; 1.3719x over previous
#include <cuda_runtime.h>
#include <math.h>
#include <stdint.h>

#define MEMN 32768
#define BATCH 256
#define UNITS 128
#define IN_DIM 512

#define OFF_READ    0
#define OFF_MEMORY  (OFF_READ + BATCH*UNITS)
#define OFF_CWU     (OFF_MEMORY + MEMN*UNITS)
#define OFF_CWLU    (OFF_CWU + MEMN*BATCH)
#define OFF_CWR     (OFF_CWLU + MEMN*BATCH)
#define OFF_CWW     (OFF_CWR + MEMN*BATCH)
#define OFF_H       (OFF_CWW + MEMN*BATCH)
#define OFF_C       (OFF_H + BATCH*UNITS)

#define PA 132
#define PB 136

typedef unsigned long long ull;

// scratch (device globals: no allocation allowed)
__device__ float g_h[BATCH*UNITS];
__device__ float g_hT[UNITS*BATCH];          // [unit][batch]
__device__ float g_kinv[BATCH];
__device__ ull   g_colenc[BATCH];
__device__ float g_colmin[BATCH];
__device__ int   g_cnt[MEMN];

__device__ __forceinline__ unsigned ordf(float f) {
    unsigned u = __float_as_uint(f);
    return (u & 0x80000000u) ? ~u : (u | 0x80000000u);
}

__device__ __forceinline__ void mma_tf32(float* d, const unsigned* a, const unsigned* b) {
    asm volatile(
        "mma.sync.aligned.m16n8k8.row.col.f32.tf32.tf32.f32 "
        "{%0,%1,%2,%3}, {%4,%5,%6,%7}, {%8,%9}, {%0,%1,%2,%3};"
        : "+f"(d[0]), "+f"(d[1]), "+f"(d[2]), "+f"(d[3])
        : "r"(a[0]), "r"(a[1]), "r"(a[2]), "r"(a[3]), "r"(b[0]), "r"(b[1]));
}

__device__ __forceinline__ unsigned rna_tf32(float a) {
    unsigned r;
    asm("cvt.rna.tf32.f32 %0, %1;" : "=r"(r) : "f"(a));
    return r;
}
__device__ __forceinline__ void split2(float a, unsigned& hi, unsigned& lo) {
    unsigned h;
    asm("cvt.rna.tf32.f32 %0, %1;" : "=r"(h) : "f"(a));
    hi = h;
    lo = __float_as_uint(a - __uint_as_float(h));
}

// ---------------- LSTM cell ----------------
__global__ void k_lstm(const float* __restrict__ inputs, const float* __restrict__ r_tm1,
                       const float* __restrict__ h_tm1, const float* __restrict__ c_tm1,
                       const float* __restrict__ Wk, const float* __restrict__ Wr,
                       const float* __restrict__ bias, float* __restrict__ out) {
    __shared__ float sA[16][128];
    __shared__ float sB[128][64];
    int t = threadIdx.x;
    int utile = blockIdx.x, btile = blockIdx.y;
    int ul = t & 15, bl = t >> 4;
    float acc[4] = {0.f, 0.f, 0.f, 0.f};

    for (int kc = 0; kc < 6; kc++) {
        #pragma unroll
        for (int p = 0; p < 2; p++) {
            int i = t + p * 256;
            int row = i >> 5, c4 = (i & 31) * 4;
            int b = btile * 16 + row;
            const float* src;
            if (kc < 4)       src = inputs + b * IN_DIM + kc * 128 + c4;
            else if (kc == 4) src = r_tm1 + b * UNITS + c4;
            else              src = h_tm1 + b * UNITS + c4;
            *(float4*)&sA[row][c4] = *(const float4*)src;
        }
        #pragma unroll
        for (int p = 0; p < 8; p++) {
            int i = t + p * 256;
            int k = i >> 4, c4 = (i & 15) * 4;
            int q = c4 >> 4, jr = c4 & 15;
            int jc = utile * 16 + jr + q * 128;
            float4 v;
            if (kc < 5) v = *(const float4*)(Wk + (kc * 128 + k) * 512 + jc);
            else        v = *(const float4*)(Wr + k * 512 + jc);
            *(float4*)&sB[k][c4] = v;
        }
        __syncthreads();
        #pragma unroll 8
        for (int k = 0; k < 128; k++) {
            float a = sA[bl][k];
            acc[0] += a * sB[k][ul];
            acc[1] += a * sB[k][16 + ul];
            acc[2] += a * sB[k][32 + ul];
            acc[3] += a * sB[k][48 + ul];
        }
        __syncthreads();
    }
    int b = btile * 16 + bl, u = utile * 16 + ul;
    float zi = acc[0] + bias[u];
    float zf = acc[1] + bias[128 + u];
    float zg = acc[2] + bias[256 + u];
    float zo = acc[3] + bias[384 + u];
    float si = 1.f / (1.f + expf(-zi));
    float sf = 1.f / (1.f + expf(-zf));
    float so = 1.f / (1.f + expf(-zo));
    float cn = sf * c_tm1[b * UNITS + u] + si * tanhf(zg);
    float hn = so * tanhf(cn);
    out[OFF_H + b * UNITS + u] = hn;
    out[OFF_C + b * UNITS + u] = cn;
    g_h[b * UNITS + u] = hn;
}

// ---------------- key inverse norms + h transpose + init scratch ----------
// grid 32 x 256. Also clears out_read, g_cnt, g_colenc (folded k_init).
__global__ void k_knorm(float* __restrict__ out_read) {
    int t = threadIdx.x, w = t >> 5, l = t & 31;
    int b = blockIdx.x * 8 + w;
    float s = 0.f;
    #pragma unroll
    for (int i = 0; i < 4; i++) { float v = g_h[b * UNITS + l + 32 * i]; s += v * v; }
    #pragma unroll
    for (int o = 16; o; o >>= 1) s += __shfl_xor_sync(0xffffffffu, s, o);
    if (l == 0) g_kinv[b] = rsqrtf(fmaxf(s, 1e-12f));
    #pragma unroll
    for (int p = 0; p < 4; p++) {
        int idx = blockIdx.x * 1024 + p * 256 + t;
        g_hT[(idx & 127) * BATCH + (idx >> 7)] = g_h[idx];
        g_cnt[idx] = 0;
        out_read[idx] = 0.f;
    }
    if (blockIdx.x == 0) g_colenc[t] = 0xFFFFFFFFFFFFFFFFull;
}

// ---------------- FUSED: cos GEMM + softmax + ww/wu + col-min --------------
// grid 1024 (32 m-rows each, ~3.5 waves for phase mixing), 256 thr, 8 warps.
// Warp tile 32m x 32n. Coalesced epilogue. (round-13 proven config)
__global__ void __launch_bounds__(256, 2)
k_fuse(const float* __restrict__ mptr, const float* __restrict__ wr_tm1,
       const float* __restrict__ wlu_tm1, const float* __restrict__ wu_tm1,
       const float* __restrict__ wgate, float* __restrict__ out) {
    extern __shared__ float sm[];
    float* sA    = sm;                       // 32*132 = 4224
    float* sB    = sA + 32 * 132;            // 64*264 = 16896 (mainloop B; later wr staging)
    float* sKinv = sB + 64 * 264;            // 256
    float* sSS   = sKinv + 256;              // 32
    float* sRmax = sSS + 32;                 // 256 ([32][8])
    float* sRsum = sRmax + 256;              // 256
    ull*   sEnc  = (ull*)(sRsum + 256);      // 256 ull
    float* sWr   = sB;                       // [32][264] staging

    int t = threadIdx.x;
    int lane = t & 31, wid = t >> 5;
    int qr = lane >> 2, qc = lane & 3;
    int mbase = blockIdx.x * 32;
    int wn = wid * 32;

    // stage A [32 rows][128 k]
    #pragma unroll
    for (int i = 0; i < 4; i++) {
        int g = t + i * 256;
        int r = g >> 5, c4 = (g & 31) << 2;
        *(float4*)&sA[r * 132 + c4] = *(const float4*)(mptr + (mbase + r) * UNITS + c4);
    }
    sKinv[t] = g_kinv[t];
    sEnc[t] = 0xFFFFFFFFFFFFFFFFull;
    __syncthreads();
    if (t < 32) {
        float ss = 0.f;
        #pragma unroll
        for (int i = 0; i < 32; i++) {
            float4 v = *(float4*)&sA[t * 132 + i * 4];
            ss += v.x * v.x + v.y * v.y + v.z * v.z + v.w * v.w;
        }
        sSS[t] = rsqrtf(fmaxf(ss, 1e-12f));
    }

    float acc[2][4][4];
    #pragma unroll
    for (int i = 0; i < 2; i++)
        #pragma unroll
        for (int j = 0; j < 4; j++)
            #pragma unroll
            for (int q = 0; q < 4; q++) acc[i][j][q] = 0.f;

    for (int kc = 0; kc < 2; kc++) {
        #pragma unroll
        for (int i = 0; i < 16; i++) {
            int g = t + i * 256;
            int r = g >> 6, c4 = (g & 63) << 2;
            *(float4*)&sB[r * 264 + c4] = *(const float4*)(g_hT + (kc * 64 + r) * BATCH + c4);
        }
        __syncthreads();
        #pragma unroll
        for (int ks = 0; ks < 8; ks++) {
            int kbA = kc * 64 + ks * 8;
            int kbB = ks * 8;
            unsigned ah[2][4], al[2][4], bb[4][2];
            #pragma unroll
            for (int mt = 0; mt < 2; mt++) {
                int rb = mt * 16;
                split2(sA[(rb + qr) * 132 + kbA + qc],         ah[mt][0], al[mt][0]);
                split2(sA[(rb + 8 + qr) * 132 + kbA + qc],     ah[mt][1], al[mt][1]);
                split2(sA[(rb + qr) * 132 + kbA + 4 + qc],     ah[mt][2], al[mt][2]);
                split2(sA[(rb + 8 + qr) * 132 + kbA + 4 + qc], ah[mt][3], al[mt][3]);
            }
            #pragma unroll
            for (int nt = 0; nt < 4; nt++) {
                int cb = wn + nt * 8;
                bb[nt][0] = rna_tf32(sB[(kbB + qc) * 264 + cb + qr]);
                bb[nt][1] = rna_tf32(sB[(kbB + 4 + qc) * 264 + cb + qr]);
            }
            #pragma unroll
            for (int mt = 0; mt < 2; mt++)
                #pragma unroll
                for (int nt = 0; nt < 4; nt++) {
                    mma_tf32(acc[mt][nt], ah[mt], bb[nt]);
                    mma_tf32(acc[mt][nt], al[mt], bb[nt]);
                }
        }
        __syncthreads();
    }

    // ---- scale to cosine ----
    #pragma unroll
    for (int mt = 0; mt < 2; mt++) {
        float s0 = sSS[mt * 16 + qr];
        float s1 = sSS[mt * 16 + qr + 8];
        #pragma unroll
        for (int nt = 0; nt < 4; nt++) {
            float k0 = sKinv[wn + nt * 8 + 2 * qc];
            float k1 = sKinv[wn + nt * 8 + 2 * qc + 1];
            acc[mt][nt][0] *= s0 * k0;
            acc[mt][nt][1] *= s0 * k1;
            acc[mt][nt][2] *= s1 * k0;
            acc[mt][nt][3] *= s1 * k1;
        }
    }

    // ---- row max ----
    float rmax[2][2];
    #pragma unroll
    for (int mt = 0; mt < 2; mt++)
        #pragma unroll
        for (int h = 0; h < 2; h++) {
            float m = -1e30f;
            #pragma unroll
            for (int nt = 0; nt < 4; nt++) {
                m = fmaxf(m, acc[mt][nt][2 * h]);
                m = fmaxf(m, acc[mt][nt][2 * h + 1]);
            }
            m = fmaxf(m, __shfl_xor_sync(0xffffffffu, m, 1));
            m = fmaxf(m, __shfl_xor_sync(0xffffffffu, m, 2));
            rmax[mt][h] = m;
        }
    if (qc == 0) {
        #pragma unroll
        for (int mt = 0; mt < 2; mt++)
            #pragma unroll
            for (int h = 0; h < 2; h++)
                sRmax[(mt * 16 + qr + h * 8) * 8 + wid] = rmax[mt][h];
    }
    __syncthreads();
    #pragma unroll
    for (int mt = 0; mt < 2; mt++)
        #pragma unroll
        for (int h = 0; h < 2; h++) {
            int rl = (mt * 16 + qr + h * 8) * 8;
            float m = sRmax[rl];
            #pragma unroll
            for (int q = 1; q < 8; q++) m = fmaxf(m, sRmax[rl + q]);
            rmax[mt][h] = m;
        }

    // ---- exp in place + row sum ----
    float rsum[2][2];
    #pragma unroll
    for (int mt = 0; mt < 2; mt++)
        #pragma unroll
        for (int h = 0; h < 2; h++) {
            float s = 0.f;
            float m = rmax[mt][h];
            #pragma unroll
            for (int nt = 0; nt < 4; nt++) {
                float e0 = __expf(acc[mt][nt][2 * h] - m);
                float e1 = __expf(acc[mt][nt][2 * h + 1] - m);
                acc[mt][nt][2 * h] = e0;
                acc[mt][nt][2 * h + 1] = e1;
                s += e0 + e1;
            }
            s += __shfl_xor_sync(0xffffffffu, s, 1);
            s += __shfl_xor_sync(0xffffffffu, s, 2);
            rsum[mt][h] = s;
        }
    if (qc == 0) {
        #pragma unroll
        for (int mt = 0; mt < 2; mt++)
            #pragma unroll
            for (int h = 0; h < 2; h++)
                sRsum[(mt * 16 + qr + h * 8) * 8 + wid] = rsum[mt][h];
    }
    __syncthreads();
    float rinv[2][2];
    #pragma unroll
    for (int mt = 0; mt < 2; mt++)
        #pragma unroll
        for (int h = 0; h < 2; h++) {
            int rl = (mt * 16 + qr + h * 8) * 8;
            float s = sRsum[rl];
            #pragma unroll
            for (int q = 1; q < 8; q++) s += sRsum[rl + q];
            rinv[mt][h] = 1.f / s;
        }

    // ---- stage wr into smem (sB dead) ----
    #pragma unroll
    for (int mt = 0; mt < 2; mt++)
        #pragma unroll
        for (int h = 0; h < 2; h++) {
            int rowl = mt * 16 + qr + h * 8;
            float inv = rinv[mt][h];
            #pragma unroll
            for (int nt = 0; nt < 4; nt++) {
                int col = wn + nt * 8 + 2 * qc;
                float2 wrp = make_float2(acc[mt][nt][2 * h] * inv, acc[mt][nt][2 * h + 1] * inv);
                *(float2*)&sWr[rowl * 264 + col] = wrp;
            }
        }
    __syncthreads();

    // ---- coalesced epilogue: thread t owns col-float4 (t&63), rows (t>>6)+4i ----
    float wg = 1.f / (1.f + __expf(-wgate[0]));
    float omw = 1.f - wg;
    int col4 = (t & 63) * 4;
    ull emin[4] = {~0ull, ~0ull, ~0ull, ~0ull};

    #pragma unroll 4
    for (int i = 0; i < 8; i++) {
        int rowl = (t >> 6) + i * 4;
        int rg = mbase + rowl;
        int idx = rg * BATCH + col4;
        float4 wr4 = *(float4*)&sWr[rowl * 264 + col4];
        float4 wrt = *(const float4*)(wr_tm1 + idx);
        float4 wlt = *(const float4*)(wlu_tm1 + idx);
        float4 wut = *(const float4*)(wu_tm1 + idx);
        float4 ww4, wu4;
        ww4.x = wg * wrt.x + omw + wlt.x;  ww4.y = wg * wrt.y + omw + wlt.y;
        ww4.z = wg * wrt.z + omw + wlt.z;  ww4.w = wg * wrt.w + omw + wlt.w;
        wu4.x = 0.95f * wut.x + wr4.x + ww4.x;  wu4.y = 0.95f * wut.y + wr4.y + ww4.y;
        wu4.z = 0.95f * wut.z + wr4.z + ww4.z;  wu4.w = 0.95f * wut.w + wr4.w + ww4.w;
        *(float4*)&out[OFF_CWR + idx] = wr4;
        *(float4*)&out[OFF_CWW + idx] = ww4;
        *(float4*)&out[OFF_CWU + idx] = wu4;
        ull lw = (ull)(0xFFFFFFFFu - (unsigned)rg);
        ull e0 = ((ull)ordf(wu4.x) << 32) | lw;
        ull e1 = ((ull)ordf(wu4.y) << 32) | lw;
        ull e2 = ((ull)ordf(wu4.z) << 32) | lw;
        ull e3 = ((ull)ordf(wu4.w) << 32) | lw;
        emin[0] = (e0 < emin[0]) ? e0 : emin[0];
        emin[1] = (e1 < emin[1]) ? e1 : emin[1];
        emin[2] = (e2 < emin[2]) ? e2 : emin[2];
        emin[3] = (e3 < emin[3]) ? e3 : emin[3];
    }
    #pragma unroll
    for (int j = 0; j < 4; j++)
        atomicMin(&sEnc[col4 + j], emin[j]);
    __syncthreads();
    atomicMin(&g_colenc[t], sEnc[t]);
}

// ---------------- finalize argmin ---------------- 1 x 256
__global__ void k_fin() {
    int c = threadIdx.x;
    ull e = g_colenc[c];
    unsigned hi = (unsigned)(e >> 32);
    unsigned bits = (hi & 0x80000000u) ? (hi & 0x7FFFFFFFu) : ~hi;
    g_colmin[c] = __uint_as_float(bits);
    int idx = (int)(0xFFFFFFFFu - (unsigned)(e & 0xFFFFFFFFull));
    atomicAdd(&g_cnt[idx], 1);
}

// ---------------- read = c_wr.T @ m_tm1, 2-MMA split, split-K, dbl-buffered -
#define RD_WO (64 * 72)
#define RD_MO (64 * 136)
#define RD_LOAD(it, buf) { \
    int kb0 = kchunk * 512 + (it) * 64; \
    _Pragma("unroll") \
    for (int i = 0; i < 4; i++) { \
        int g = t + i * 256; \
        int r = g >> 4, c4 = (g & 15) << 2; \
        *(float4*)&sW[(buf) * RD_WO + r * 72 + c4] = *(const float4*)(cwr + (kb0 + r) * BATCH + bbase + c4); \
    } \
    _Pragma("unroll") \
    for (int i = 0; i < 8; i++) { \
        int g = t + i * 256; \
        int r = g >> 5, c4 = (g & 31) << 2; \
        *(float4*)&sM[(buf) * RD_MO + r * 136 + c4] = *(const float4*)(mptr + (kb0 + r) * UNITS + c4); \
    } \
}

__global__ void __launch_bounds__(256, 2) k_read(const float* __restrict__ mptr,
                                                 const float* __restrict__ cwr,
                                                 float* __restrict__ out_read) {
    extern __shared__ float sm[];
    float* sW = sm;                      // [2][64][72]
    float* sM = sm + 2 * RD_WO;          // [2][64][136]

    int t = threadIdx.x;
    int lane = t & 31, wid = t >> 5;
    int qr = lane >> 2, qc = lane & 3;
    int bbase = blockIdx.x * 64;
    int kchunk = blockIdx.y;
    int wm = (wid >> 2) * 32, wn = (wid & 3) * 32;

    float acc[2][4][4];
    #pragma unroll
    for (int i = 0; i < 2; i++)
        #pragma unroll
        for (int j = 0; j < 4; j++)
            #pragma unroll
            for (int q = 0; q < 4; q++) acc[i][j][q] = 0.f;

    RD_LOAD(0, 0);
    __syncthreads();

    for (int it = 0; it < 8; it++) {
        int buf = it & 1;
        if (it < 7) { RD_LOAD(it + 1, buf ^ 1); }
        const float* cW = sW + buf * RD_WO;
        const float* cM = sM + buf * RD_MO;
        #pragma unroll
        for (int ks = 0; ks < 8; ks++) {
            int kb = ks * 8;
            unsigned ah[2][4], al[2][4], bb[4][2];
            #pragma unroll
            for (int mt = 0; mt < 2; mt++) {
                int rb = wm + mt * 16;
                split2(cW[(kb + qc) * 72 + rb + qr],         ah[mt][0], al[mt][0]);
                split2(cW[(kb + qc) * 72 + rb + 8 + qr],     ah[mt][1], al[mt][1]);
                split2(cW[(kb + 4 + qc) * 72 + rb + qr],     ah[mt][2], al[mt][2]);
                split2(cW[(kb + 4 + qc) * 72 + rb + 8 + qr], ah[mt][3], al[mt][3]);
            }
            #pragma unroll
            for (int nt = 0; nt < 4; nt++) {
                int cb = wn + nt * 8;
                bb[nt][0] = rna_tf32(cM[(kb + qc) * 136 + cb + qr]);
                bb[nt][1] = rna_tf32(cM[(kb + 4 + qc) * 136 + cb + qr]);
            }
            #pragma unroll
            for (int mt = 0; mt < 2; mt++)
                #pragma unroll
                for (int nt = 0; nt < 4; nt++) {
                    mma_tf32(acc[mt][nt], ah[mt], bb[nt]);
                    mma_tf32(acc[mt][nt], al[mt], bb[nt]);
                }
        }
        __syncthreads();
    }
    #pragma unroll
    for (int mt = 0; mt < 2; mt++) {
        int r0 = bbase + wm + mt * 16 + qr;
        #pragma unroll
        for (int nt = 0; nt < 4; nt++) {
            int c = wn + nt * 8 + 2 * qc;
            atomicAdd(&out_read[r0 * UNITS + c],           acc[mt][nt][0]);
            atomicAdd(&out_read[r0 * UNITS + c + 1],       acc[mt][nt][1]);
            atomicAdd(&out_read[(r0 + 8) * UNITS + c],     acc[mt][nt][2]);
            atomicAdd(&out_read[(r0 + 8) * UNITS + c + 1], acc[mt][nt][3]);
        }
    }
}

// ---------------- memory = c_ww @ h + (256 - cnt[m]) * m_tm1 ---------------
__global__ void __launch_bounds__(256) k_mem(const float* __restrict__ mptr,
                                             const float* __restrict__ cww,
                                             float* __restrict__ out_mem) {
    extern __shared__ float sm[];
    float* sA = sm;                  // [64][PA]
    float* sB = sm + 64 * PA;        // [128][PB]

    int t = threadIdx.x;
    int lane = t & 31, wid = t >> 5;
    int qr = lane >> 2, qc = lane & 3;
    int mbase = blockIdx.x * 64;
    int wm = (wid >> 2) * 32, wn = (wid & 3) * 32;

    float acc[2][4][4];
    #pragma unroll
    for (int i = 0; i < 2; i++)
        #pragma unroll
        for (int j = 0; j < 4; j++)
            #pragma unroll
            for (int q = 0; q < 4; q++) acc[i][j][q] = 0.f;

    for (int kc = 0; kc < 2; kc++) {
        #pragma unroll
        for (int i = 0; i < 8; i++) {
            int g = t + i * 256;
            int r = g >> 5, c4 = (g & 31) << 2;
            *(float4*)&sA[r * PA + c4] = *(const float4*)(cww + (mbase + r) * BATCH + kc * 128 + c4);
        }
        #pragma unroll
        for (int i = 0; i < 16; i++) {
            int g = t + i * 256;
            int r = g >> 5, c4 = (g & 31) << 2;
            *(float4*)&sB[r * PB + c4] = *(const float4*)(g_h + (kc * 128 + r) * UNITS + c4);
        }
        __syncthreads();
        #pragma unroll
        for (int ks = 0; ks < 16; ks++) {
            int kb = ks * 8;
            unsigned ah[2][4], al[2][4], bb[4][2];
            #pragma unroll
            for (int mt = 0; mt < 2; mt++) {
                int rb = wm + mt * 16;
                split2(sA[(rb + qr) * PA + kb + qc],         ah[mt][0], al[mt][0]);
                split2(sA[(rb + 8 + qr) * PA + kb + qc],     ah[mt][1], al[mt][1]);
                split2(sA[(rb + qr) * PA + kb + 4 + qc],     ah[mt][2], al[mt][2]);
                split2(sA[(rb + 8 + qr) * PA + kb + 4 + qc], ah[mt][3], al[mt][3]);
            }
            #pragma unroll
            for (int nt = 0; nt < 4; nt++) {
                int cb = wn + nt * 8;
                bb[nt][0] = rna_tf32(sB[(kb + qc) * PB + cb + qr]);
                bb[nt][1] = rna_tf32(sB[(kb + 4 + qc) * PB + cb + qr]);
            }
            #pragma unroll
            for (int mt = 0; mt < 2; mt++)
                #pragma unroll
                for (int nt = 0; nt < 4; nt++) {
                    mma_tf32(acc[mt][nt], ah[mt], bb[nt]);
                    mma_tf32(acc[mt][nt], al[mt], bb[nt]);
                }
        }
        __syncthreads();
    }

    // ---- stage result fragments into smem (sA dead) ----
    #pragma unroll
    for (int mt = 0; mt < 2; mt++) {
        int rowl = wm + mt * 16 + qr;
        #pragma unroll
        for (int nt = 0; nt < 4; nt++) {
            int c = wn + nt * 8 + 2 * qc;
            *(float2*)&sA[rowl * PA + c]       = make_float2(acc[mt][nt][0], acc[mt][nt][1]);
            *(float2*)&sA[(rowl + 8) * PA + c] = make_float2(acc[mt][nt][2], acc[mt][nt][3]);
        }
    }
    __syncthreads();

    // ---- coalesced pass: warp owns a full 128-float row ----
    int colq = lane * 4;
    #pragma unroll
    for (int i = 0; i < 8; i++) {
        int rowl = wid + i * 8;
        int rg = mbase + rowl;
        float f = (float)(BATCH - g_cnt[rg]);
        float4 mv = *(const float4*)(mptr + rg * UNITS + colq);
        float4 rv = *(float4*)&sA[rowl * PA + colq];
        float4 o;
        o.x = rv.x + f * mv.x;
        o.y = rv.y + f * mv.y;
        o.z = rv.z + f * mv.z;
        o.w = rv.w + f * mv.w;
        *(float4*)(out_mem + rg * UNITS + colq) = o;
    }
}

// ---------------- c_wlu = (c_wu <= colmin) ----------------
__global__ void k_wlu(const float* __restrict__ out_cwu, float* __restrict__ out_cwlu) {
    __shared__ float smin[256];
    smin[threadIdx.x] = g_colmin[threadIdx.x];
    __syncthreads();
    const int total = MEMN * BATCH / 4;
    for (int i4 = blockIdx.x * 256 + threadIdx.x; i4 < total; i4 += gridDim.x * 256) {
        float4 v = *(const float4*)(out_cwu + i4 * 4);
        int c = (i4 & 63) * 4;
        float4 o;
        o.x = (v.x <= smin[c])     ? 1.f : 0.f;
        o.y = (v.y <= smin[c + 1]) ? 1.f : 0.f;
        o.z = (v.z <= smin[c + 2]) ? 1.f : 0.f;
        o.w = (v.w <= smin[c + 3]) ? 1.f : 0.f;
        *(float4*)(out_cwlu + i4 * 4) = o;
    }
}

extern "C" void kernel_launch(void* const* d_in, const int* in_sizes, int n_in,
                              void* d_out, int out_size) {
    (void)in_sizes; (void)n_in; (void)out_size;
    const float* inputs   = (const float*)d_in[0];
    const float* r_tm1    = (const float*)d_in[1];
    const float* m_tm1    = (const float*)d_in[2];
    const float* c_wu_tm1 = (const float*)d_in[3];
    const float* c_wlu_tm1= (const float*)d_in[4];
    const float* c_wr_tm1 = (const float*)d_in[5];
    const float* h_tm1    = (const float*)d_in[7];
    const float* c_tm1    = (const float*)d_in[8];
    const float* Wk       = (const float*)d_in[9];
    const float* Wr       = (const float*)d_in[10];
    const float* bias     = (const float*)d_in[11];
    const float* wgate    = (const float*)d_in[12];
    float* out = (float*)d_out;

    const int smem_fuse = (32 * 132 + 64 * 264 + 256 + 32 + 256 + 256 + 512) * 4;  // 89728
    const int smem_read = 2 * (RD_WO + RD_MO) * 4;                                 // 106496
    const int smem_mem  = (64 * PA + 128 * PB) * 4;                                // 103424

    cudaFuncSetAttribute(k_fuse, cudaFuncAttributeMaxDynamicSharedMemorySize, smem_fuse);
    cudaFuncSetAttribute(k_read, cudaFuncAttributeMaxDynamicSharedMemorySize, smem_read);
    cudaFuncSetAttribute(k_mem,  cudaFuncAttributeMaxDynamicSharedMemorySize, smem_mem);

    k_lstm<<<dim3(8, 16), 256>>>(inputs, r_tm1, h_tm1, c_tm1, Wk, Wr, bias, out);
    k_knorm<<<32, 256>>>(out + OFF_READ);
    k_fuse<<<1024, 256, smem_fuse>>>(m_tm1, c_wr_tm1, c_wlu_tm1, c_wu_tm1, wgate, out);
    k_fin<<<1, 256>>>();
    k_read<<<dim3(4, 64), 256, smem_read>>>(m_tm1, out + OFF_CWR, out + OFF_READ);
    k_mem<<<512, 256, smem_mem>>>(m_tm1, out + OFF_CWW, out + OFF_MEMORY);
    k_wlu<<<2048, 256>>>(out + OFF_CWU, out + OFF_CWLU);
}

// round 16
// speedup vs baseline: 1.3967x; 1.0181x over previous
#include <cuda_runtime.h>
#include <math.h>
#include <stdint.h>

#define MEMN 32768
#define BATCH 256
#define UNITS 128
#define IN_DIM 512

#define OFF_READ    0
#define OFF_MEMORY  (OFF_READ + BATCH*UNITS)
#define OFF_CWU     (OFF_MEMORY + MEMN*UNITS)
#define OFF_CWLU    (OFF_CWU + MEMN*BATCH)
#define OFF_CWR     (OFF_CWLU + MEMN*BATCH)
#define OFF_CWW     (OFF_CWR + MEMN*BATCH)
#define OFF_H       (OFF_CWW + MEMN*BATCH)
#define OFF_C       (OFF_H + BATCH*UNITS)

#define PA 132
#define PB 136

typedef unsigned long long ull;

// scratch (device globals: no allocation allowed)
__device__ float g_h[BATCH*UNITS];
__device__ float g_hT[UNITS*BATCH];          // [unit][batch]
__device__ float g_kinv[BATCH];
__device__ ull   g_colenc[BATCH];

__device__ __forceinline__ unsigned ordf(float f) {
    unsigned u = __float_as_uint(f);
    return (u & 0x80000000u) ? ~u : (u | 0x80000000u);
}
__device__ __forceinline__ float dec_min(ull e) {
    unsigned hi = (unsigned)(e >> 32);
    unsigned bits = (hi & 0x80000000u) ? (hi & 0x7FFFFFFFu) : ~hi;
    return __uint_as_float(bits);
}
__device__ __forceinline__ int dec_idx(ull e) {
    return (int)(0xFFFFFFFFu - (unsigned)(e & 0xFFFFFFFFull));
}

__device__ __forceinline__ void mma_tf32(float* d, const unsigned* a, const unsigned* b) {
    asm volatile(
        "mma.sync.aligned.m16n8k8.row.col.f32.tf32.tf32.f32 "
        "{%0,%1,%2,%3}, {%4,%5,%6,%7}, {%8,%9}, {%0,%1,%2,%3};"
        : "+f"(d[0]), "+f"(d[1]), "+f"(d[2]), "+f"(d[3])
        : "r"(a[0]), "r"(a[1]), "r"(a[2]), "r"(a[3]), "r"(b[0]), "r"(b[1]));
}

__device__ __forceinline__ unsigned rna_tf32(float a) {
    unsigned r;
    asm("cvt.rna.tf32.f32 %0, %1;" : "=r"(r) : "f"(a));
    return r;
}
__device__ __forceinline__ void split2(float a, unsigned& hi, unsigned& lo) {
    unsigned h;
    asm("cvt.rna.tf32.f32 %0, %1;" : "=r"(h) : "f"(a));
    hi = h;
    lo = __float_as_uint(a - __uint_as_float(h));
}

// ---------------- LSTM cell ----------------
__global__ void k_lstm(const float* __restrict__ inputs, const float* __restrict__ r_tm1,
                       const float* __restrict__ h_tm1, const float* __restrict__ c_tm1,
                       const float* __restrict__ Wk, const float* __restrict__ Wr,
                       const float* __restrict__ bias, float* __restrict__ out) {
    __shared__ float sA[16][128];
    __shared__ float sB[128][64];
    int t = threadIdx.x;
    int utile = blockIdx.x, btile = blockIdx.y;
    int ul = t & 15, bl = t >> 4;
    float acc[4] = {0.f, 0.f, 0.f, 0.f};

    for (int kc = 0; kc < 6; kc++) {
        #pragma unroll
        for (int p = 0; p < 2; p++) {
            int i = t + p * 256;
            int row = i >> 5, c4 = (i & 31) * 4;
            int b = btile * 16 + row;
            const float* src;
            if (kc < 4)       src = inputs + b * IN_DIM + kc * 128 + c4;
            else if (kc == 4) src = r_tm1 + b * UNITS + c4;
            else              src = h_tm1 + b * UNITS + c4;
            *(float4*)&sA[row][c4] = *(const float4*)src;
        }
        #pragma unroll
        for (int p = 0; p < 8; p++) {
            int i = t + p * 256;
            int k = i >> 4, c4 = (i & 15) * 4;
            int q = c4 >> 4, jr = c4 & 15;
            int jc = utile * 16 + jr + q * 128;
            float4 v;
            if (kc < 5) v = *(const float4*)(Wk + (kc * 128 + k) * 512 + jc);
            else        v = *(const float4*)(Wr + k * 512 + jc);
            *(float4*)&sB[k][c4] = v;
        }
        __syncthreads();
        #pragma unroll 8
        for (int k = 0; k < 128; k++) {
            float a = sA[bl][k];
            acc[0] += a * sB[k][ul];
            acc[1] += a * sB[k][16 + ul];
            acc[2] += a * sB[k][32 + ul];
            acc[3] += a * sB[k][48 + ul];
        }
        __syncthreads();
    }
    int b = btile * 16 + bl, u = utile * 16 + ul;
    float zi = acc[0] + bias[u];
    float zf = acc[1] + bias[128 + u];
    float zg = acc[2] + bias[256 + u];
    float zo = acc[3] + bias[384 + u];
    float si = 1.f / (1.f + expf(-zi));
    float sf = 1.f / (1.f + expf(-zf));
    float so = 1.f / (1.f + expf(-zo));
    float cn = sf * c_tm1[b * UNITS + u] + si * tanhf(zg);
    float hn = so * tanhf(cn);
    out[OFF_H + b * UNITS + u] = hn;
    out[OFF_C + b * UNITS + u] = cn;
    g_h[b * UNITS + u] = hn;
}

// ---------------- key inverse norms + h transpose + init scratch ----------
__global__ void k_knorm(float* __restrict__ out_read) {
    int t = threadIdx.x, w = t >> 5, l = t & 31;
    int b = blockIdx.x * 8 + w;
    float s = 0.f;
    #pragma unroll
    for (int i = 0; i < 4; i++) { float v = g_h[b * UNITS + l + 32 * i]; s += v * v; }
    #pragma unroll
    for (int o = 16; o; o >>= 1) s += __shfl_xor_sync(0xffffffffu, s, o);
    if (l == 0) g_kinv[b] = rsqrtf(fmaxf(s, 1e-12f));
    #pragma unroll
    for (int p = 0; p < 4; p++) {
        int idx = blockIdx.x * 1024 + p * 256 + t;
        g_hT[(idx & 127) * BATCH + (idx >> 7)] = g_h[idx];
        if (idx < BATCH * UNITS) out_read[idx] = 0.f;
    }
    if (blockIdx.x == 0) g_colenc[t] = 0xFFFFFFFFFFFFFFFFull;
}

// ---------------- FUSED: cos GEMM + softmax + ww/wu + col-min --------------
// grid 1024 (32 m-rows each), 256 thr, 8 warps, warp tile 32m x 32n.
__global__ void __launch_bounds__(256, 2)
k_fuse(const float* __restrict__ mptr, const float* __restrict__ wr_tm1,
       const float* __restrict__ wlu_tm1, const float* __restrict__ wu_tm1,
       const float* __restrict__ wgate, float* __restrict__ out) {
    extern __shared__ float sm[];
    float* sA    = sm;                       // 32*132 = 4224
    float* sB    = sA + 32 * 132;            // 64*264 = 16896 (mainloop B; later wr staging)
    float* sKinv = sB + 64 * 264;            // 256
    float* sSS   = sKinv + 256;              // 32
    float* sRmax = sSS + 32;                 // 256 ([32][8])
    float* sRsum = sRmax + 256;              // 256
    ull*   sEnc  = (ull*)(sRsum + 256);      // 256 ull
    float* sWr   = sB;                       // [32][264] staging

    int t = threadIdx.x;
    int lane = t & 31, wid = t >> 5;
    int qr = lane >> 2, qc = lane & 3;
    int mbase = blockIdx.x * 32;
    int wn = wid * 32;

    // stage A [32 rows][128 k]
    #pragma unroll
    for (int i = 0; i < 4; i++) {
        int g = t + i * 256;
        int r = g >> 5, c4 = (g & 31) << 2;
        *(float4*)&sA[r * 132 + c4] = *(const float4*)(mptr + (mbase + r) * UNITS + c4);
    }
    sKinv[t] = g_kinv[t];
    sEnc[t] = 0xFFFFFFFFFFFFFFFFull;
    __syncthreads();
    if (t < 32) {
        float ss = 0.f;
        #pragma unroll
        for (int i = 0; i < 32; i++) {
            float4 v = *(float4*)&sA[t * 132 + i * 4];
            ss += v.x * v.x + v.y * v.y + v.z * v.z + v.w * v.w;
        }
        sSS[t] = rsqrtf(fmaxf(ss, 1e-12f));
    }

    float acc[2][4][4];
    #pragma unroll
    for (int i = 0; i < 2; i++)
        #pragma unroll
        for (int j = 0; j < 4; j++)
            #pragma unroll
            for (int q = 0; q < 4; q++) acc[i][j][q] = 0.f;

    for (int kc = 0; kc < 2; kc++) {
        #pragma unroll
        for (int i = 0; i < 16; i++) {
            int g = t + i * 256;
            int r = g >> 6, c4 = (g & 63) << 2;
            *(float4*)&sB[r * 264 + c4] = *(const float4*)(g_hT + (kc * 64 + r) * BATCH + c4);
        }
        __syncthreads();
        #pragma unroll
        for (int ks = 0; ks < 8; ks++) {
            int kbA = kc * 64 + ks * 8;
            int kbB = ks * 8;
            unsigned ah[2][4], al[2][4], bb[4][2];
            #pragma unroll
            for (int mt = 0; mt < 2; mt++) {
                int rb = mt * 16;
                split2(sA[(rb + qr) * 132 + kbA + qc],         ah[mt][0], al[mt][0]);
                split2(sA[(rb + 8 + qr) * 132 + kbA + qc],     ah[mt][1], al[mt][1]);
                split2(sA[(rb + qr) * 132 + kbA + 4 + qc],     ah[mt][2], al[mt][2]);
                split2(sA[(rb + 8 + qr) * 132 + kbA + 4 + qc], ah[mt][3], al[mt][3]);
            }
            #pragma unroll
            for (int nt = 0; nt < 4; nt++) {
                int cb = wn + nt * 8;
                bb[nt][0] = rna_tf32(sB[(kbB + qc) * 264 + cb + qr]);
                bb[nt][1] = rna_tf32(sB[(kbB + 4 + qc) * 264 + cb + qr]);
            }
            #pragma unroll
            for (int mt = 0; mt < 2; mt++)
                #pragma unroll
                for (int nt = 0; nt < 4; nt++) {
                    mma_tf32(acc[mt][nt], ah[mt], bb[nt]);
                    mma_tf32(acc[mt][nt], al[mt], bb[nt]);
                }
        }
        __syncthreads();
    }

    // ---- scale to cosine ----
    #pragma unroll
    for (int mt = 0; mt < 2; mt++) {
        float s0 = sSS[mt * 16 + qr];
        float s1 = sSS[mt * 16 + qr + 8];
        #pragma unroll
        for (int nt = 0; nt < 4; nt++) {
            float k0 = sKinv[wn + nt * 8 + 2 * qc];
            float k1 = sKinv[wn + nt * 8 + 2 * qc + 1];
            acc[mt][nt][0] *= s0 * k0;
            acc[mt][nt][1] *= s0 * k1;
            acc[mt][nt][2] *= s1 * k0;
            acc[mt][nt][3] *= s1 * k1;
        }
    }

    // ---- row max ----
    float rmax[2][2];
    #pragma unroll
    for (int mt = 0; mt < 2; mt++)
        #pragma unroll
        for (int h = 0; h < 2; h++) {
            float m = -1e30f;
            #pragma unroll
            for (int nt = 0; nt < 4; nt++) {
                m = fmaxf(m, acc[mt][nt][2 * h]);
                m = fmaxf(m, acc[mt][nt][2 * h + 1]);
            }
            m = fmaxf(m, __shfl_xor_sync(0xffffffffu, m, 1));
            m = fmaxf(m, __shfl_xor_sync(0xffffffffu, m, 2));
            rmax[mt][h] = m;
        }
    if (qc == 0) {
        #pragma unroll
        for (int mt = 0; mt < 2; mt++)
            #pragma unroll
            for (int h = 0; h < 2; h++)
                sRmax[(mt * 16 + qr + h * 8) * 8 + wid] = rmax[mt][h];
    }
    __syncthreads();
    #pragma unroll
    for (int mt = 0; mt < 2; mt++)
        #pragma unroll
        for (int h = 0; h < 2; h++) {
            int rl = (mt * 16 + qr + h * 8) * 8;
            float m = sRmax[rl];
            #pragma unroll
            for (int q = 1; q < 8; q++) m = fmaxf(m, sRmax[rl + q]);
            rmax[mt][h] = m;
        }

    // ---- exp in place + row sum ----
    float rsum[2][2];
    #pragma unroll
    for (int mt = 0; mt < 2; mt++)
        #pragma unroll
        for (int h = 0; h < 2; h++) {
            float s = 0.f;
            float m = rmax[mt][h];
            #pragma unroll
            for (int nt = 0; nt < 4; nt++) {
                float e0 = __expf(acc[mt][nt][2 * h] - m);
                float e1 = __expf(acc[mt][nt][2 * h + 1] - m);
                acc[mt][nt][2 * h] = e0;
                acc[mt][nt][2 * h + 1] = e1;
                s += e0 + e1;
            }
            s += __shfl_xor_sync(0xffffffffu, s, 1);
            s += __shfl_xor_sync(0xffffffffu, s, 2);
            rsum[mt][h] = s;
        }
    if (qc == 0) {
        #pragma unroll
        for (int mt = 0; mt < 2; mt++)
            #pragma unroll
            for (int h = 0; h < 2; h++)
                sRsum[(mt * 16 + qr + h * 8) * 8 + wid] = rsum[mt][h];
    }
    __syncthreads();
    float rinv[2][2];
    #pragma unroll
    for (int mt = 0; mt < 2; mt++)
        #pragma unroll
        for (int h = 0; h < 2; h++) {
            int rl = (mt * 16 + qr + h * 8) * 8;
            float s = sRsum[rl];
            #pragma unroll
            for (int q = 1; q < 8; q++) s += sRsum[rl + q];
            rinv[mt][h] = 1.f / s;
        }

    // ---- stage wr into smem (sB dead) ----
    #pragma unroll
    for (int mt = 0; mt < 2; mt++)
        #pragma unroll
        for (int h = 0; h < 2; h++) {
            int rowl = mt * 16 + qr + h * 8;
            float inv = rinv[mt][h];
            #pragma unroll
            for (int nt = 0; nt < 4; nt++) {
                int col = wn + nt * 8 + 2 * qc;
                float2 wrp = make_float2(acc[mt][nt][2 * h] * inv, acc[mt][nt][2 * h + 1] * inv);
                *(float2*)&sWr[rowl * 264 + col] = wrp;
            }
        }
    __syncthreads();

    // ---- coalesced epilogue ----
    float wg = 1.f / (1.f + __expf(-wgate[0]));
    float omw = 1.f - wg;
    int col4 = (t & 63) * 4;
    ull emin[4] = {~0ull, ~0ull, ~0ull, ~0ull};

    #pragma unroll 4
    for (int i = 0; i < 8; i++) {
        int rowl = (t >> 6) + i * 4;
        int rg = mbase + rowl;
        int idx = rg * BATCH + col4;
        float4 wr4 = *(float4*)&sWr[rowl * 264 + col4];
        float4 wrt = *(const float4*)(wr_tm1 + idx);
        float4 wlt = *(const float4*)(wlu_tm1 + idx);
        float4 wut = *(const float4*)(wu_tm1 + idx);
        float4 ww4, wu4;
        ww4.x = wg * wrt.x + omw + wlt.x;  ww4.y = wg * wrt.y + omw + wlt.y;
        ww4.z = wg * wrt.z + omw + wlt.z;  ww4.w = wg * wrt.w + omw + wlt.w;
        wu4.x = 0.95f * wut.x + wr4.x + ww4.x;  wu4.y = 0.95f * wut.y + wr4.y + ww4.y;
        wu4.z = 0.95f * wut.z + wr4.z + ww4.z;  wu4.w = 0.95f * wut.w + wr4.w + ww4.w;
        *(float4*)&out[OFF_CWR + idx] = wr4;
        *(float4*)&out[OFF_CWW + idx] = ww4;
        *(float4*)&out[OFF_CWU + idx] = wu4;
        ull lw = (ull)(0xFFFFFFFFu - (unsigned)rg);
        ull e0 = ((ull)ordf(wu4.x) << 32) | lw;
        ull e1 = ((ull)ordf(wu4.y) << 32) | lw;
        ull e2 = ((ull)ordf(wu4.z) << 32) | lw;
        ull e3 = ((ull)ordf(wu4.w) << 32) | lw;
        emin[0] = (e0 < emin[0]) ? e0 : emin[0];
        emin[1] = (e1 < emin[1]) ? e1 : emin[1];
        emin[2] = (e2 < emin[2]) ? e2 : emin[2];
        emin[3] = (e3 < emin[3]) ? e3 : emin[3];
    }
    #pragma unroll
    for (int j = 0; j < 4; j++)
        atomicMin(&sEnc[col4 + j], emin[j]);
    __syncthreads();
    atomicMin(&g_colenc[t], sEnc[t]);
}

// ---------------- read = c_wr.T @ m_tm1, 2-MMA split, split-K, dbl-buffered -
#define RD_WO (64 * 72)
#define RD_MO (64 * 136)
#define RD_LOAD(it, buf) { \
    int kb0 = kchunk * 512 + (it) * 64; \
    _Pragma("unroll") \
    for (int i = 0; i < 4; i++) { \
        int g = t + i * 256; \
        int r = g >> 4, c4 = (g & 15) << 2; \
        *(float4*)&sW[(buf) * RD_WO + r * 72 + c4] = *(const float4*)(cwr + (kb0 + r) * BATCH + bbase + c4); \
    } \
    _Pragma("unroll") \
    for (int i = 0; i < 8; i++) { \
        int g = t + i * 256; \
        int r = g >> 5, c4 = (g & 31) << 2; \
        *(float4*)&sM[(buf) * RD_MO + r * 136 + c4] = *(const float4*)(mptr + (kb0 + r) * UNITS + c4); \
    } \
}

__global__ void __launch_bounds__(256, 2) k_read(const float* __restrict__ mptr,
                                                 const float* __restrict__ cwr,
                                                 float* __restrict__ out_read) {
    extern __shared__ float sm[];
    float* sW = sm;                      // [2][64][72]
    float* sM = sm + 2 * RD_WO;          // [2][64][136]

    int t = threadIdx.x;
    int lane = t & 31, wid = t >> 5;
    int qr = lane >> 2, qc = lane & 3;
    int bbase = blockIdx.x * 64;
    int kchunk = blockIdx.y;
    int wm = (wid >> 2) * 32, wn = (wid & 3) * 32;

    float acc[2][4][4];
    #pragma unroll
    for (int i = 0; i < 2; i++)
        #pragma unroll
        for (int j = 0; j < 4; j++)
            #pragma unroll
            for (int q = 0; q < 4; q++) acc[i][j][q] = 0.f;

    RD_LOAD(0, 0);
    __syncthreads();

    for (int it = 0; it < 8; it++) {
        int buf = it & 1;
        if (it < 7) { RD_LOAD(it + 1, buf ^ 1); }
        const float* cW = sW + buf * RD_WO;
        const float* cM = sM + buf * RD_MO;
        #pragma unroll
        for (int ks = 0; ks < 8; ks++) {
            int kb = ks * 8;
            unsigned ah[2][4], al[2][4], bb[4][2];
            #pragma unroll
            for (int mt = 0; mt < 2; mt++) {
                int rb = wm + mt * 16;
                split2(cW[(kb + qc) * 72 + rb + qr],         ah[mt][0], al[mt][0]);
                split2(cW[(kb + qc) * 72 + rb + 8 + qr],     ah[mt][1], al[mt][1]);
                split2(cW[(kb + 4 + qc) * 72 + rb + qr],     ah[mt][2], al[mt][2]);
                split2(cW[(kb + 4 + qc) * 72 + rb + 8 + qr], ah[mt][3], al[mt][3]);
            }
            #pragma unroll
            for (int nt = 0; nt < 4; nt++) {
                int cb = wn + nt * 8;
                bb[nt][0] = rna_tf32(cM[(kb + qc) * 136 + cb + qr]);
                bb[nt][1] = rna_tf32(cM[(kb + 4 + qc) * 136 + cb + qr]);
            }
            #pragma unroll
            for (int mt = 0; mt < 2; mt++)
                #pragma unroll
                for (int nt = 0; nt < 4; nt++) {
                    mma_tf32(acc[mt][nt], ah[mt], bb[nt]);
                    mma_tf32(acc[mt][nt], al[mt], bb[nt]);
                }
        }
        __syncthreads();
    }
    #pragma unroll
    for (int mt = 0; mt < 2; mt++) {
        int r0 = bbase + wm + mt * 16 + qr;
        #pragma unroll
        for (int nt = 0; nt < 4; nt++) {
            int c = wn + nt * 8 + 2 * qc;
            atomicAdd(&out_read[r0 * UNITS + c],           acc[mt][nt][0]);
            atomicAdd(&out_read[r0 * UNITS + c + 1],       acc[mt][nt][1]);
            atomicAdd(&out_read[(r0 + 8) * UNITS + c],     acc[mt][nt][2]);
            atomicAdd(&out_read[(r0 + 8) * UNITS + c + 1], acc[mt][nt][3]);
        }
    }
}

// ---------------- memory = c_ww @ h + (256 - cnt[m]) * m_tm1 ---------------
// cnt computed inline by scanning g_colenc (k_fin folded in).
__global__ void __launch_bounds__(256) k_mem(const float* __restrict__ mptr,
                                             const float* __restrict__ cww,
                                             float* __restrict__ out_mem) {
    extern __shared__ float sm[];
    float* sA = sm;                  // [64][PA]
    float* sB = sm + 64 * PA;        // [128][PB]
    int*  sCnt = (int*)(sB + 128 * PB);  // [64]

    int t = threadIdx.x;
    int lane = t & 31, wid = t >> 5;
    int qr = lane >> 2, qc = lane & 3;
    int mbase = blockIdx.x * 64;
    int wm = (wid >> 2) * 32, wn = (wid & 3) * 32;

    if (t < 64) sCnt[t] = 0;
    __syncthreads();
    // scan column argmins; count those landing in this CTA's 64 rows
    {
        ull e = g_colenc[t];
        int idx = dec_idx(e);
        if (idx >= mbase && idx < mbase + 64) atomicAdd(&sCnt[idx - mbase], 1);
    }

    float acc[2][4][4];
    #pragma unroll
    for (int i = 0; i < 2; i++)
        #pragma unroll
        for (int j = 0; j < 4; j++)
            #pragma unroll
            for (int q = 0; q < 4; q++) acc[i][j][q] = 0.f;

    for (int kc = 0; kc < 2; kc++) {
        #pragma unroll
        for (int i = 0; i < 8; i++) {
            int g = t + i * 256;
            int r = g >> 5, c4 = (g & 31) << 2;
            *(float4*)&sA[r * PA + c4] = *(const float4*)(cww + (mbase + r) * BATCH + kc * 128 + c4);
        }
        #pragma unroll
        for (int i = 0; i < 16; i++) {
            int g = t + i * 256;
            int r = g >> 5, c4 = (g & 31) << 2;
            *(float4*)&sB[r * PB + c4] = *(const float4*)(g_h + (kc * 128 + r) * UNITS + c4);
        }
        __syncthreads();
        #pragma unroll
        for (int ks = 0; ks < 16; ks++) {
            int kb = ks * 8;
            unsigned ah[2][4], al[2][4], bb[4][2];
            #pragma unroll
            for (int mt = 0; mt < 2; mt++) {
                int rb = wm + mt * 16;
                split2(sA[(rb + qr) * PA + kb + qc],         ah[mt][0], al[mt][0]);
                split2(sA[(rb + 8 + qr) * PA + kb + qc],     ah[mt][1], al[mt][1]);
                split2(sA[(rb + qr) * PA + kb + 4 + qc],     ah[mt][2], al[mt][2]);
                split2(sA[(rb + 8 + qr) * PA + kb + 4 + qc], ah[mt][3], al[mt][3]);
            }
            #pragma unroll
            for (int nt = 0; nt < 4; nt++) {
                int cb = wn + nt * 8;
                bb[nt][0] = rna_tf32(sB[(kb + qc) * PB + cb + qr]);
                bb[nt][1] = rna_tf32(sB[(kb + 4 + qc) * PB + cb + qr]);
            }
            #pragma unroll
            for (int mt = 0; mt < 2; mt++)
                #pragma unroll
                for (int nt = 0; nt < 4; nt++) {
                    mma_tf32(acc[mt][nt], ah[mt], bb[nt]);
                    mma_tf32(acc[mt][nt], al[mt], bb[nt]);
                }
        }
        __syncthreads();
    }

    // ---- stage result fragments into smem (sA dead) ----
    #pragma unroll
    for (int mt = 0; mt < 2; mt++) {
        int rowl = wm + mt * 16 + qr;
        #pragma unroll
        for (int nt = 0; nt < 4; nt++) {
            int c = wn + nt * 8 + 2 * qc;
            *(float2*)&sA[rowl * PA + c]       = make_float2(acc[mt][nt][0], acc[mt][nt][1]);
            *(float2*)&sA[(rowl + 8) * PA + c] = make_float2(acc[mt][nt][2], acc[mt][nt][3]);
        }
    }
    __syncthreads();

    // ---- coalesced pass: warp owns a full 128-float row ----
    int colq = lane * 4;
    #pragma unroll
    for (int i = 0; i < 8; i++) {
        int rowl = wid + i * 8;
        int rg = mbase + rowl;
        float f = (float)(BATCH - sCnt[rowl]);
        float4 mv = *(const float4*)(mptr + rg * UNITS + colq);
        float4 rv = *(float4*)&sA[rowl * PA + colq];
        float4 o;
        o.x = rv.x + f * mv.x;
        o.y = rv.y + f * mv.y;
        o.z = rv.z + f * mv.z;
        o.w = rv.w + f * mv.w;
        *(float4*)(out_mem + rg * UNITS + colq) = o;
    }
}

// ---------------- c_wlu = (c_wu <= colmin), colmin decoded inline ----------
__global__ void k_wlu(const float* __restrict__ out_cwu, float* __restrict__ out_cwlu) {
    __shared__ float smin[256];
    smin[threadIdx.x] = dec_min(g_colenc[threadIdx.x]);
    __syncthreads();
    const int total = MEMN * BATCH / 4;
    for (int i4 = blockIdx.x * 256 + threadIdx.x; i4 < total; i4 += gridDim.x * 256) {
        float4 v = *(const float4*)(out_cwu + i4 * 4);
        int c = (i4 & 63) * 4;
        float4 o;
        o.x = (v.x <= smin[c])     ? 1.f : 0.f;
        o.y = (v.y <= smin[c + 1]) ? 1.f : 0.f;
        o.z = (v.z <= smin[c + 2]) ? 1.f : 0.f;
        o.w = (v.w <= smin[c + 3]) ? 1.f : 0.f;
        *(float4*)(out_cwlu + i4 * 4) = o;
    }
}

extern "C" void kernel_launch(void* const* d_in, const int* in_sizes, int n_in,
                              void* d_out, int out_size) {
    (void)in_sizes; (void)n_in; (void)out_size;
    const float* inputs   = (const float*)d_in[0];
    const float* r_tm1    = (const float*)d_in[1];
    const float* m_tm1    = (const float*)d_in[2];
    const float* c_wu_tm1 = (const float*)d_in[3];
    const float* c_wlu_tm1= (const float*)d_in[4];
    const float* c_wr_tm1 = (const float*)d_in[5];
    const float* h_tm1    = (const float*)d_in[7];
    const float* c_tm1    = (const float*)d_in[8];
    const float* Wk       = (const float*)d_in[9];
    const float* Wr       = (const float*)d_in[10];
    const float* bias     = (const float*)d_in[11];
    const float* wgate    = (const float*)d_in[12];
    float* out = (float*)d_out;

    const int smem_fuse = (32 * 132 + 64 * 264 + 256 + 32 + 256 + 256 + 512) * 4;  // 89728
    const int smem_read = 2 * (RD_WO + RD_MO) * 4;                                 // 106496
    const int smem_mem  = (64 * PA + 128 * PB + 64) * 4;                           // 103680

    cudaFuncSetAttribute(k_fuse, cudaFuncAttributeMaxDynamicSharedMemorySize, smem_fuse);
    cudaFuncSetAttribute(k_read, cudaFuncAttributeMaxDynamicSharedMemorySize, smem_read);
    cudaFuncSetAttribute(k_mem,  cudaFuncAttributeMaxDynamicSharedMemorySize, smem_mem);

    k_lstm<<<dim3(8, 16), 256>>>(inputs, r_tm1, h_tm1, c_tm1, Wk, Wr, bias, out);
    k_knorm<<<32, 256>>>(out + OFF_READ);
    k_fuse<<<1024, 256, smem_fuse>>>(m_tm1, c_wr_tm1, c_wlu_tm1, c_wu_tm1, wgate, out);
    k_read<<<dim3(4, 64), 256, smem_read>>>(m_tm1, out + OFF_CWR, out + OFF_READ);
    k_mem<<<512, 256, smem_mem>>>(m_tm1, out + OFF_CWW, out + OFF_MEMORY);
    k_wlu<<<2048, 256>>>(out + OFF_CWU, out + OFF_CWLU);
}